// round 9
// baseline (speedup 1.0000x reference)
#include <cuda_runtime.h>

// CFConv: y[i] = sum_{e: idx_i[e]==i} x[idx_j[e]] * Wij[e]
// x:[50000,64] f32, Wij:[E=1.25M,64] f32, idx_i sorted.
//
// R9: W stream taken OUT of shared memory (sequential -> direct __ldcs LDG.128
// depth-2 register pipeline + prefetch.global.L2 at distance 12); only the
// random x gather uses the cp.async SMEM ring (D=8). Halves L1tex/smem-port
// wavefronts per edge. Half-warp float4 lanes; sorted-segment register
// accumulation; plain stores for interior segments; red.global.add.v4.f32 at
// task boundaries.

#define FEAT   64
#define F4     (FEAT / 4)      // 16 float4 per feature row
#define HALF   64              // edges per half-warp task
#define CHUNK  (2 * HALF)      // edges per warp
#define D      8               // x-gather ring depth
#define PF     12              // W L2-prefetch distance (edges)
#define WPB    2               // warps per block
#define TPB    (WPB * 32)

__device__ __forceinline__ void red_add_f4(float* p, float4 v) {
    asm volatile("red.global.add.v4.f32 [%0], {%1,%2,%3,%4};"
                 :: "l"(p), "f"(v.x), "f"(v.y), "f"(v.z), "f"(v.w)
                 : "memory");
}

__device__ __forceinline__ void fma4(float4& a, float4 x, float4 w) {
    a.x = fmaf(x.x, w.x, a.x);
    a.y = fmaf(x.y, w.y, a.y);
    a.z = fmaf(x.z, w.z, a.z);
    a.w = fmaf(x.w, w.w, a.w);
}

__device__ __forceinline__ void flush(float* __restrict__ y, int seg, int fl,
                                      float4 acc, bool& first)
{
    float* dst = y + (size_t)seg * FEAT + fl * 4;
    if (first) { red_add_f4(dst, acc); first = false; }
    else       { *reinterpret_cast<float4*>(dst) = acc; }  // exclusive interior
}

__device__ __forceinline__ void cp16(void* smem_dst, const void* gmem_src) {
    unsigned           ds = (unsigned)__cvta_generic_to_shared(smem_dst);
    unsigned long long gs = (unsigned long long)__cvta_generic_to_global(gmem_src);
    asm volatile("cp.async.cg.shared.global [%0], [%1], 16;"
                 :: "r"(ds), "l"(gs) : "memory");
}

__device__ __forceinline__ void pf_l2(const void* p) {
    asm volatile("prefetch.global.L2 [%0];" :: "l"(p));
}
template <typename T>
__device__ __forceinline__ void pf_l1(const T* p) {
    asm volatile("prefetch.global.L1 [%0];" :: "l"(p));
}

template <typename IdxT>
__device__ __forceinline__ void cfconv_body(
    const float4* __restrict__ X4, const float4* __restrict__ W4,
    const IdxT* __restrict__ idx_i, const IdxT* __restrict__ idx_j,
    float* __restrict__ y,
    float4 (&sX)[WPB][D][32],
    int w, int lane, int fl, long long s, int cnt)
{
    const float4* wp = W4 + (size_t)s * F4 + fl;

    int    prev;
    bool   first = true;               // first segment may start before s
    float4 acc   = make_float4(0.f, 0.f, 0.f, 0.f);

    if (cnt == HALF) {
        // -------- pipelined full-task path --------
        // x ring prologue: fill all D stages (one commit group per stage)
        #pragma unroll
        for (int d = 0; d < D; ++d) {
            int jj = (int)idx_j[s + d];
            cp16(&sX[w][d][lane], X4 + (size_t)jj * F4 + fl);
            asm volatile("cp.async.commit_group;" ::: "memory");
        }
        // W register pipeline (depth-2) + warm L2 ahead
        float4 wA = __ldcs(wp);
        float4 wB = __ldcs(wp + F4);
        if ((fl & 7) == 0) {                 // 2 lanes per half cover 256B row
            #pragma unroll
            for (int d = 2; d < PF; d += 2) pf_l2(wp + (size_t)d * F4);
        }

        int ci = (int)idx_i[s];        // consume idx, depth-1 staged
        prev   = ci;
        int pj = (int)idx_j[s + D];    // gather idx for first in-loop prefetch

        for (int k = 0; k < HALF; ++k) {
            asm volatile("cp.async.wait_group %0;" :: "n"(D - 1) : "memory");
            int st = k % D;
            float4 xv = sX[w][st][lane];

            // x-gather prefetch for edge k+D into the slot just consumed
            if (k + D < HALF) {
                cp16(&sX[w][st][lane], X4 + (size_t)pj * F4 + fl);
                pf_l1(idx_i + s + k + D);      // keep idx_i line L1-hot
            }
            asm volatile("cp.async.commit_group;" ::: "memory");

            // W: load k+2 (clamped), prefetch k+PF into L2 (2 lanes/half)
            int nw = k + 2;  if (nw > HALF - 1) nw = HALF - 1;
            float4 wN = __ldcs(wp + (size_t)nw * F4);
            if (((fl & 7) == 0) && (k + PF < HALF))
                pf_l2(wp + (size_t)(k + PF) * F4);

            // stage next-iteration indices (clamped; L1 hits)
            int nc = k + 1;     if (nc > HALF - 1) nc = HALF - 1;
            int np = k + D + 1; if (np > HALF - 1) np = HALF - 1;
            int ci_n = (int)idx_i[s + nc];
            pj       = (int)idx_j[s + np];

            // consume edge k
            if (ci != prev) {
                flush(y, prev, fl, acc, first);
                acc  = make_float4(0.f, 0.f, 0.f, 0.f);
                prev = ci;
            }
            fma4(acc, xv, wA);
            ci = ci_n;
            wA = wB; wB = wN;
        }
    } else {
        // -------- scalar tail path (at most one partial task) --------
        int    ic = (int)idx_i[s];
        int    jc = (int)idx_j[s];
        float4 wc = __ldcs(wp);
        float4 xc = X4[(size_t)jc * F4 + fl];
        prev = ic;
        for (int k = 1; k < cnt; ++k) {
            int    in_ = (int)idx_i[s + k];
            int    jn  = (int)idx_j[s + k];
            float4 wn  = __ldcs(wp + (size_t)k * F4);
            float4 xn  = X4[(size_t)jn * F4 + fl];
            if (ic != prev) {
                flush(y, prev, fl, acc, first);
                acc  = make_float4(0.f, 0.f, 0.f, 0.f);
                prev = ic;
            }
            fma4(acc, xc, wc);
            ic = in_; wc = wn; xc = xn;
        }
        if (ic != prev) {
            flush(y, prev, fl, acc, first);
            acc  = make_float4(0.f, 0.f, 0.f, 0.f);
            prev = ic;
        }
        fma4(acc, xc, wc);
    }

    // final segment may extend into the next task -> atomic
    red_add_f4(y + (size_t)prev * FEAT + fl * 4, acc);
}

__global__ __launch_bounds__(TPB) void cfconv_kernel(
    const float4* __restrict__ X4, const float4* __restrict__ W4,
    const void* __restrict__ ii_p, const void* __restrict__ jj_p,
    float* __restrict__ y, int E)
{
    __shared__ float4 sX[WPB][D][32];

    int tid  = threadIdx.x;
    int w    = tid >> 5;
    int lane = tid & 31;
    int half = lane >> 4;
    int fl   = lane & 15;

    int gwarp = blockIdx.x * WPB + w;
    long long base = (long long)gwarp * CHUNK;
    if (base >= E) return;
    long long s = base + (long long)half * HALF;
    if (s >= E) return;
    long long se = s + HALF; if (se > E) se = E;
    int cnt = (int)(se - s);

    // dtype probe (uniform): LE int64 -> int32 word at odd position (E/2)|1 is
    // a zero high word; int32 -> sorted idx_i median ~N/2 != 0.
    int probe = reinterpret_cast<const int*>(ii_p)[(E / 2) | 1];
    if (probe == 0) {
        cfconv_body<long long>(X4, W4,
                               reinterpret_cast<const long long*>(ii_p),
                               reinterpret_cast<const long long*>(jj_p),
                               y, sX, w, lane, fl, s, cnt);
    } else {
        cfconv_body<int>(X4, W4,
                         reinterpret_cast<const int*>(ii_p),
                         reinterpret_cast<const int*>(jj_p),
                         y, sX, w, lane, fl, s, cnt);
    }
}

extern "C" void kernel_launch(void* const* d_in, const int* in_sizes, int n_in,
                              void* d_out, int out_size)
{
    const float* x   = (const float*)d_in[0];   // [N, 64]
    const float* Wij = (const float*)d_in[1];   // [E, 64]
    const void*  ii  = d_in[2];                 // [E] int64 or int32
    const void*  jj  = d_in[3];                 // [E] int64 or int32
    float*       y   = (float*)d_out;           // [N, 64]

    int E = in_sizes[1] / FEAT;

    // zero output (memset node — graph-capturable)
    cudaMemsetAsync(d_out, 0, (size_t)out_size * sizeof(float), 0);

    int nwarps  = (E + CHUNK - 1) / CHUNK;
    int nblocks = (nwarps + WPB - 1) / WPB;
    cfconv_kernel<<<nblocks, TPB>>>((const float4*)x, (const float4*)Wij,
                                    ii, jj, y, E);
}